// round 15
// baseline (speedup 1.0000x reference)
#include <cuda_runtime.h>
#include <math.h>
#include <stdint.h>

// Fixed shapes
#define BN 8192
#define DN 2048
#define ROWB (DN * 4)         // 8192 B/row
#define TINV 10.0f            // 1/T, T = 0.1
#define NTHR 256              // 8 warps/block
#define WPB  (NTHR / 32)
#define NBLK 296              // 2 blocks/SM on 148 SMs
#define TOTW (NBLK * WPB)     // 2368 warps

// Scratch (device globals)
__device__ double g_partE[NBLK];
__device__ double g_partW[NBLK];
__device__ double g_partL[NBLK];
__device__ unsigned int g_count;

__device__ __forceinline__ float warp_sum(float v) {
    #pragma unroll
    for (int o = 16; o; o >>= 1) v += __shfl_xor_sync(0xffffffffu, v, o);
    return v;
}
__device__ __forceinline__ double warp_sum_d(double v) {
    #pragma unroll
    for (int o = 16; o; o >>= 1) v += __shfl_xor_sync(0xffffffffu, v, o);
    return v;
}
// DRAM -> L2 prefetch of a full 8KB row. No SM-side consumer: not subject to
// the per-SM outstanding-line cap. Subsequent LDGs hit L2 (~240cyc vs 577).
__device__ __forceinline__ void prefetch_row_l2(const void* p) {
    asm volatile("cp.async.bulk.prefetch.L2.global [%0], %1;"
                 :: "l"(p), "r"((uint32_t)ROWB) : "memory");
}

__global__ void __launch_bounds__(NTHR, 2)
fused_kernel(const float* __restrict__ embed,
             const float* __restrict__ ee,
             const float* __restrict__ labels,
             float* __restrict__ out) {
    __shared__ float4  sa[DN / 4];            // raw anchor, 8 KB
    __shared__ float   redf[WPB];
    __shared__ double  redE[WPB], redW[WPB], redL[WPB];
    __shared__ bool    s_last;

    const int tid  = threadIdx.x;
    const int warp = tid >> 5;
    const int lane = tid & 31;
    const int wg   = blockIdx.x * WPB + warp;
    const char* eeb = reinterpret_cast<const char*>(ee);

    // ---- prologue: prefetch this warp's first row into L2 immediately.
    //      Anchor staging below provides the lead time. ----
    if (lane == 0 && wg < BN) prefetch_row_l2(eeb + (size_t)wg * ROWB);

    // ---- Stage anchor into shared + ||e0||^2 partials; ONE sync. ----
    const float4* e4 = reinterpret_cast<const float4*>(embed);
    float na2p = 0.f;
    #pragma unroll
    for (int i = 0; i < (DN / 4) / NTHR; i++) {     // 2 iterations
        float4 v = e4[i * NTHR + tid];
        sa[i * NTHR + tid] = v;
        na2p = fmaf(v.x, v.x, na2p);
        na2p = fmaf(v.y, v.y, na2p);
        na2p = fmaf(v.z, v.z, na2p);
        na2p = fmaf(v.w, v.w, na2p);
    }
    na2p = warp_sum(na2p);
    if (lane == 0) redf[warp] = na2p;
    __syncthreads();

    float anorm2 = 0.f;
    #pragma unroll
    for (int i = 0; i < WPB; i++) anorm2 += redf[i];
    const float norm0 = sqrtf(anorm2);
    const float inv   = 1.0f / fmaxf(norm0, 1e-12f);     // F.normalize
    const float na    = fmaxf(norm0 * inv, 1e-6f);       // cos eps
    const float scale = TINV * inv / na;                 // neg = -scale*dot/nb

    // ---- Stream: prefetch next row to L2, front-batch 16x LDG.128 (plain,
    //      L2-allocating) for the current (already-prefetched) row. ----
    double E = 0.0, W = 0.0, L = 0.0;
    for (int row = wg; row < BN; row += TOTW) {
        // prefetch one full iteration ahead (lead >> DRAM latency)
        long nr = (long)row + TOTW;
        if (lane == 0 && nr < BN) prefetch_row_l2(eeb + nr * (long)ROWB);

        const float4* x4 = reinterpret_cast<const float4*>(eeb + (size_t)row * ROWB);

        // Phase A: batch ALL 16 loads, no consumers in between.
        float4 x[16];
        #pragma unroll
        for (int i = 0; i < 16; i++) x[i] = x4[i * 32 + lane];

        // Phase B: FMA against smem anchor; 4 split accumulators each.
        float d0 = 0.f, d1 = 0.f, d2 = 0.f, d3 = 0.f;
        float m0 = 0.f, m1 = 0.f, m2 = 0.f, m3 = 0.f;
        #pragma unroll
        for (int i = 0; i < 16; i += 4) {
            float4 a0 = sa[(i + 0) * 32 + lane];
            float4 a1 = sa[(i + 1) * 32 + lane];
            float4 a2 = sa[(i + 2) * 32 + lane];
            float4 a3 = sa[(i + 3) * 32 + lane];
            d0 = fmaf(x[i+0].x, a0.x, d0); d0 = fmaf(x[i+0].y, a0.y, d0);
            d0 = fmaf(x[i+0].z, a0.z, d0); d0 = fmaf(x[i+0].w, a0.w, d0);
            m0 = fmaf(x[i+0].x, x[i+0].x, m0); m0 = fmaf(x[i+0].y, x[i+0].y, m0);
            m0 = fmaf(x[i+0].z, x[i+0].z, m0); m0 = fmaf(x[i+0].w, x[i+0].w, m0);
            d1 = fmaf(x[i+1].x, a1.x, d1); d1 = fmaf(x[i+1].y, a1.y, d1);
            d1 = fmaf(x[i+1].z, a1.z, d1); d1 = fmaf(x[i+1].w, a1.w, d1);
            m1 = fmaf(x[i+1].x, x[i+1].x, m1); m1 = fmaf(x[i+1].y, x[i+1].y, m1);
            m1 = fmaf(x[i+1].z, x[i+1].z, m1); m1 = fmaf(x[i+1].w, x[i+1].w, m1);
            d2 = fmaf(x[i+2].x, a2.x, d2); d2 = fmaf(x[i+2].y, a2.y, d2);
            d2 = fmaf(x[i+2].z, a2.z, d2); d2 = fmaf(x[i+2].w, a2.w, d2);
            m2 = fmaf(x[i+2].x, x[i+2].x, m2); m2 = fmaf(x[i+2].y, x[i+2].y, m2);
            m2 = fmaf(x[i+2].z, x[i+2].z, m2); m2 = fmaf(x[i+2].w, x[i+2].w, m2);
            d3 = fmaf(x[i+3].x, a3.x, d3); d3 = fmaf(x[i+3].y, a3.y, d3);
            d3 = fmaf(x[i+3].z, a3.z, d3); d3 = fmaf(x[i+3].w, a3.w, d3);
            m3 = fmaf(x[i+3].x, x[i+3].x, m3); m3 = fmaf(x[i+3].y, x[i+3].y, m3);
            m3 = fmaf(x[i+3].z, x[i+3].z, m3); m3 = fmaf(x[i+3].w, x[i+3].w, m3);
        }
        float dot = warp_sum((d0 + d1) + (d2 + d3));
        float n2  = warp_sum((m0 + m1) + (m2 + m3));

        if (lane == 0 && row != 0) {
            float nb  = fmaxf(sqrtf(n2), 1e-6f);
            float neg = -scale * dot / nb;
            float lj  = labels[row];
            E += (double)expf(neg);
            W += (double)lj * (double)neg;
            L += (double)lj;
        }
    }

    // ---- Block partials -> scratch ----
    if (lane == 0) { redE[warp] = E; redW[warp] = W; redL[warp] = L; }
    __syncthreads();
    if (warp == 0) {
        double e = (lane < WPB) ? redE[lane] : 0.0;
        double w = (lane < WPB) ? redW[lane] : 0.0;
        double l = (lane < WPB) ? redL[lane] : 0.0;
        e = warp_sum_d(e); w = warp_sum_d(w); l = warp_sum_d(l);
        if (lane == 0) {
            g_partE[blockIdx.x] = e;
            g_partW[blockIdx.x] = w;
            g_partL[blockIdx.x] = l;
            __threadfence();
            unsigned int c = atomicAdd(&g_count, 1u);
            s_last = (c == NBLK - 1);
        }
    }
    __syncthreads();

    // ---- Last block reduces ALL NBLK partials (strided) and finalizes ----
    if (s_last) {
        double e = 0.0, w = 0.0, l = 0.0;
        for (int idx = tid; idx < NBLK; idx += NTHR) {
            e += g_partE[idx]; w += g_partW[idx]; l += g_partL[idx];
        }
        e = warp_sum_d(e); w = warp_sum_d(w); l = warp_sum_d(l);
        if (lane == 0) { redE[warp] = e; redW[warp] = w; redL[warp] = l; }
        __syncthreads();
        if (tid == 0) {
            double Et = 0, Wt = 0, Lt = 0;
            #pragma unroll
            for (int i = 0; i < WPB; i++) { Et += redE[i]; Wt += redW[i]; Lt += redL[i]; }
            double l0   = (double)labels[0];
            double E0   = 1e-12 + Et;
            double C0   = 1e-12 + l0 * Lt;
            double logE = log(E0);
            double L0   = (l0 / C0) * (logE * Lt - Wt);
            out[0] = (float)(L0 / (double)BN);
            g_count = 0;                                  // reset for replay
        }
    }
}

extern "C" void kernel_launch(void* const* d_in, const int* in_sizes, int n_in,
                              void* d_out, int out_size) {
    const float* embed         = (const float*)d_in[0];
    const float* embed_enhance = (const float*)d_in[1];
    const float* labels        = (const float*)d_in[2];
    float* out = (float*)d_out;

    fused_kernel<<<NBLK, NTHR>>>(embed, embed_enhance, labels, out);
}

// round 16
// speedup vs baseline: 1.0345x; 1.0345x over previous
#include <cuda_runtime.h>
#include <math.h>

// Fixed shapes
#define BN 8192
#define DN 2048
#define TINV 10.0f            // 1/T, T = 0.1
#define NTHR 256              // 8 warps/block
#define WPB  (NTHR / 32)
#define NBLK 296              // 2 blocks/SM on 148 SMs
#define TOTW (NBLK * WPB)     // 2368 warps

// Scratch (device globals)
__device__ double g_partE[NBLK];
__device__ double g_partW[NBLK];
__device__ double g_partL[NBLK];
__device__ unsigned int g_count;

__device__ __forceinline__ float warp_sum(float v) {
    #pragma unroll
    for (int o = 16; o; o >>= 1) v += __shfl_xor_sync(0xffffffffu, v, o);
    return v;
}
__device__ __forceinline__ double warp_sum_d(double v) {
    #pragma unroll
    for (int o = 16; o; o >>= 1) v += __shfl_xor_sync(0xffffffffu, v, o);
    return v;
}

__global__ void __launch_bounds__(NTHR, 2)
fused_kernel(const float* __restrict__ embed,
             const float* __restrict__ ee,
             const float* __restrict__ labels,
             float* __restrict__ out) {
    __shared__ float4  sa[DN / 4];            // raw anchor, 8 KB
    __shared__ float   redf[WPB];
    __shared__ double  redE[WPB], redW[WPB], redL[WPB];
    __shared__ bool    s_last;

    const int tid  = threadIdx.x;
    const int warp = tid >> 5;
    const int lane = tid & 31;
    const int wg   = blockIdx.x * WPB + warp;

    // ---- Stage anchor into shared + ||e0||^2 partials; ONE sync. ----
    const float4* e4 = reinterpret_cast<const float4*>(embed);
    float na2p = 0.f;
    #pragma unroll
    for (int i = 0; i < (DN / 4) / NTHR; i++) {     // 2 iterations
        float4 v = e4[i * NTHR + tid];
        sa[i * NTHR + tid] = v;
        na2p = fmaf(v.x, v.x, na2p);
        na2p = fmaf(v.y, v.y, na2p);
        na2p = fmaf(v.z, v.z, na2p);
        na2p = fmaf(v.w, v.w, na2p);
    }
    na2p = warp_sum(na2p);
    if (lane == 0) redf[warp] = na2p;
    __syncthreads();

    float anorm2 = 0.f;
    #pragma unroll
    for (int i = 0; i < WPB; i++) anorm2 += redf[i];
    const float norm0 = sqrtf(anorm2);
    const float inv   = 1.0f / fmaxf(norm0, 1e-12f);     // F.normalize
    const float na    = fmaxf(norm0 * inv, 1e-6f);       // cos eps
    const float scale = TINV * inv / na;                 // neg = -scale*dot/nb

    // ---- Stream: front-batched 16x LDG.128 per row; even slots .cv
    //      (DRAM path, no L2 alloc), odd slots plain (L2-resident on
    //      replays). Splits traffic across the two return paths. ----
    double E = 0.0, W = 0.0, L = 0.0;
    for (int row = wg; row < BN; row += TOTW) {
        const float4* x4 = reinterpret_cast<const float4*>(ee + (size_t)row * DN);

        // Phase A: batch ALL 16 loads, no consumers in between.
        float4 x[16];
        #pragma unroll
        for (int i = 0; i < 16; i += 2) {
            x[i]     = __ldcv(&x4[i * 32 + lane]);        // .cv half
            x[i + 1] = x4[(i + 1) * 32 + lane];           // plain half
        }

        // Phase B: FMA against smem anchor; 4 split accumulators each.
        float d0 = 0.f, d1 = 0.f, d2 = 0.f, d3 = 0.f;
        float m0 = 0.f, m1 = 0.f, m2 = 0.f, m3 = 0.f;
        #pragma unroll
        for (int i = 0; i < 16; i += 4) {
            float4 a0 = sa[(i + 0) * 32 + lane];
            float4 a1 = sa[(i + 1) * 32 + lane];
            float4 a2 = sa[(i + 2) * 32 + lane];
            float4 a3 = sa[(i + 3) * 32 + lane];
            d0 = fmaf(x[i+0].x, a0.x, d0); d0 = fmaf(x[i+0].y, a0.y, d0);
            d0 = fmaf(x[i+0].z, a0.z, d0); d0 = fmaf(x[i+0].w, a0.w, d0);
            m0 = fmaf(x[i+0].x, x[i+0].x, m0); m0 = fmaf(x[i+0].y, x[i+0].y, m0);
            m0 = fmaf(x[i+0].z, x[i+0].z, m0); m0 = fmaf(x[i+0].w, x[i+0].w, m0);
            d1 = fmaf(x[i+1].x, a1.x, d1); d1 = fmaf(x[i+1].y, a1.y, d1);
            d1 = fmaf(x[i+1].z, a1.z, d1); d1 = fmaf(x[i+1].w, a1.w, d1);
            m1 = fmaf(x[i+1].x, x[i+1].x, m1); m1 = fmaf(x[i+1].y, x[i+1].y, m1);
            m1 = fmaf(x[i+1].z, x[i+1].z, m1); m1 = fmaf(x[i+1].w, x[i+1].w, m1);
            d2 = fmaf(x[i+2].x, a2.x, d2); d2 = fmaf(x[i+2].y, a2.y, d2);
            d2 = fmaf(x[i+2].z, a2.z, d2); d2 = fmaf(x[i+2].w, a2.w, d2);
            m2 = fmaf(x[i+2].x, x[i+2].x, m2); m2 = fmaf(x[i+2].y, x[i+2].y, m2);
            m2 = fmaf(x[i+2].z, x[i+2].z, m2); m2 = fmaf(x[i+2].w, x[i+2].w, m2);
            d3 = fmaf(x[i+3].x, a3.x, d3); d3 = fmaf(x[i+3].y, a3.y, d3);
            d3 = fmaf(x[i+3].z, a3.z, d3); d3 = fmaf(x[i+3].w, a3.w, d3);
            m3 = fmaf(x[i+3].x, x[i+3].x, m3); m3 = fmaf(x[i+3].y, x[i+3].y, m3);
            m3 = fmaf(x[i+3].z, x[i+3].z, m3); m3 = fmaf(x[i+3].w, x[i+3].w, m3);
        }
        float dot = warp_sum((d0 + d1) + (d2 + d3));
        float n2  = warp_sum((m0 + m1) + (m2 + m3));

        if (lane == 0 && row != 0) {
            float nb  = fmaxf(sqrtf(n2), 1e-6f);
            float neg = -scale * dot / nb;
            float lj  = labels[row];
            E += (double)expf(neg);
            W += (double)lj * (double)neg;
            L += (double)lj;
        }
    }

    // ---- Block partials -> scratch ----
    if (lane == 0) { redE[warp] = E; redW[warp] = W; redL[warp] = L; }
    __syncthreads();
    if (warp == 0) {
        double e = (lane < WPB) ? redE[lane] : 0.0;
        double w = (lane < WPB) ? redW[lane] : 0.0;
        double l = (lane < WPB) ? redL[lane] : 0.0;
        e = warp_sum_d(e); w = warp_sum_d(w); l = warp_sum_d(l);
        if (lane == 0) {
            g_partE[blockIdx.x] = e;
            g_partW[blockIdx.x] = w;
            g_partL[blockIdx.x] = l;
            __threadfence();
            unsigned int c = atomicAdd(&g_count, 1u);
            s_last = (c == NBLK - 1);
        }
    }
    __syncthreads();

    // ---- Last block reduces ALL NBLK partials (strided) and finalizes ----
    if (s_last) {
        double e = 0.0, w = 0.0, l = 0.0;
        for (int idx = tid; idx < NBLK; idx += NTHR) {
            e += g_partE[idx]; w += g_partW[idx]; l += g_partL[idx];
        }
        e = warp_sum_d(e); w = warp_sum_d(w); l = warp_sum_d(l);
        if (lane == 0) { redE[warp] = e; redW[warp] = w; redL[warp] = l; }
        __syncthreads();
        if (tid == 0) {
            double Et = 0, Wt = 0, Lt = 0;
            #pragma unroll
            for (int i = 0; i < WPB; i++) { Et += redE[i]; Wt += redW[i]; Lt += redL[i]; }
            double l0   = (double)labels[0];
            double E0   = 1e-12 + Et;
            double C0   = 1e-12 + l0 * Lt;
            double logE = log(E0);
            double L0   = (l0 / C0) * (logE * Lt - Wt);
            out[0] = (float)(L0 / (double)BN);
            g_count = 0;                                  // reset for replay
        }
    }
}

extern "C" void kernel_launch(void* const* d_in, const int* in_sizes, int n_in,
                              void* d_out, int out_size) {
    const float* embed         = (const float*)d_in[0];
    const float* embed_enhance = (const float*)d_in[1];
    const float* labels        = (const float*)d_in[2];
    float* out = (float*)d_out;

    fused_kernel<<<NBLK, NTHR>>>(embed, embed_enhance, labels, out);
}